// round 17
// baseline (speedup 1.0000x reference)
#include <cuda_runtime.h>
#include <math.h>
#include <float.h>

#define NMAX 2048
#define HID  256
#define KMAX (NMAX/2)
#define CAP  256

// ---------------- scratch (device globals) -----------------------------------
// g_A stores A1 = A + I at every level (diag forced to 1).
__device__ float g_A[NMAX*NMAX];
__device__ float g_scoreT[NMAX*NMAX];
__device__ float g_SpT[KMAX*NMAX];
__device__ float g_M2T[KMAX*NMAX];
__device__ float g_Ac[KMAX*KMAX];
__device__ float g_part[4*NMAX*HID];    // split-K partial buffer (2M floats)
__device__ float g_h[NMAX*HID];
__device__ float g_g[NMAX*HID];
__device__ float g_y[NMAX*HID];
__device__ float g_mm[NMAX*HID];
__device__ float g_xq[NMAX*HID];
__device__ float g_xnew[NMAX*HID];
__device__ float g_u[NMAX];
__device__ float g_v[NMAX];
__device__ float g_dinv[NMAX];
__device__ float g_av[NMAX];
__device__ float g_bv[NMAX];
__device__ float g_cv[NMAX];
__device__ float g_fit[NMAX];
__device__ float g_fvals[KMAX];
__device__ int   g_perm[KMAX];
__device__ float g_ro[2*HID];
__device__ int   g_nzidx[NMAX*CAP];
__device__ int   g_nzcnt[NMAX];
__device__ float g_sval[NMAX*CAP];

// ---------------- 128x128 tiled fp32 GEMM, split-K, double-buffered -----------
// OP=0: C = A@B chunk (A@B^T if TB). OP=1: masked max (A entry !=0 gates B).
// OP=2: C = A@binarize(B) chunk.
// Block: 256 threads, tile 128x128, slab depth 8, 8x8 per-thread fragment.
// Requires: M%128==0, N%128==0, Kc%8==0. Partial written to C + z*M*N.
template<bool TB, int OP>
__global__ void __launch_bounds__(256) k_gemm(
    const float* __restrict__ A, const float* __restrict__ B, float* __restrict__ C,
    int M, int N, int Kc, int lda, int ldb, int ldc)
{
    __shared__ float As[2][8][128];
    __shared__ float Bs[2][8][128];
    const int tid = threadIdx.x;
    const int tx = tid & 15, ty = tid >> 4;          // 16x16 thread grid
    const int m0 = blockIdx.y * 128, n0 = blockIdx.x * 128;
    const int ar = tid >> 1;            // 0..127 (row within tile)
    const int ak = (tid & 1) << 2;      // 0 or 4 (k offset)
    const int bk = tid >> 5;            // 0..7   (k row, non-TB B)
    const int bn = (tid & 31) << 2;     // 0..124 (col, non-TB B)
    const int kstart = blockIdx.z * Kc;
    float* Cz = C + (size_t)blockIdx.z * M * N;

    const float* Aptr = A + (size_t)(m0 + ar) * lda + kstart + ak;
    const float* Bptr = TB ? (B + (size_t)(n0 + ar) * ldb + kstart + ak)
                           : (B + (size_t)(kstart + bk) * ldb + (n0 + bn));

    float acc[8][8];
#pragma unroll
    for (int i = 0; i < 8; i++)
#pragma unroll
        for (int j = 0; j < 8; j++) acc[i][j] = (OP == 1) ? -FLT_MAX : 0.f;

    // load slab 0 into buffer 0
    {
        float4 av = *(const float4*)Aptr;
        As[0][ak+0][ar] = av.x; As[0][ak+1][ar] = av.y; As[0][ak+2][ar] = av.z; As[0][ak+3][ar] = av.w;
        float4 bv = *(const float4*)Bptr;
        if (TB) {
            Bs[0][ak+0][ar] = bv.x; Bs[0][ak+1][ar] = bv.y; Bs[0][ak+2][ar] = bv.z; Bs[0][ak+3][ar] = bv.w;
        } else {
            if (OP == 2) {
                bv.x = (bv.x != 0.f) ? 1.f : 0.f; bv.y = (bv.y != 0.f) ? 1.f : 0.f;
                bv.z = (bv.z != 0.f) ? 1.f : 0.f; bv.w = (bv.w != 0.f) ? 1.f : 0.f;
            }
            *(float4*)&Bs[0][bk][bn] = bv;
        }
    }
    __syncthreads();

    const int nslab = Kc >> 3;
    for (int s = 0; s < nslab; s++) {
        const int buf = s & 1;
        float4 avn, bvn;
        const bool more = (s + 1 < nslab);
        if (more) {
            avn = *(const float4*)(Aptr + (s + 1) * 8);
            if (TB) bvn = *(const float4*)(Bptr + (s + 1) * 8);
            else {
                bvn = *(const float4*)(Bptr + (size_t)(s + 1) * 8 * ldb);
                if (OP == 2) {
                    bvn.x = (bvn.x != 0.f) ? 1.f : 0.f; bvn.y = (bvn.y != 0.f) ? 1.f : 0.f;
                    bvn.z = (bvn.z != 0.f) ? 1.f : 0.f; bvn.w = (bvn.w != 0.f) ? 1.f : 0.f;
                }
            }
        }
#pragma unroll
        for (int kk = 0; kk < 8; kk++) {
            float4 a0 = *(const float4*)&As[buf][kk][ty << 3];
            float4 a1 = *(const float4*)&As[buf][kk][(ty << 3) + 4];
            float4 b0 = *(const float4*)&Bs[buf][kk][tx << 3];
            float4 b1 = *(const float4*)&Bs[buf][kk][(tx << 3) + 4];
            float am[8] = {a0.x, a0.y, a0.z, a0.w, a1.x, a1.y, a1.z, a1.w};
            float bm[8] = {b0.x, b0.y, b0.z, b0.w, b1.x, b1.y, b1.z, b1.w};
            if (OP != 1) {
#pragma unroll
                for (int i = 0; i < 8; i++)
#pragma unroll
                    for (int j = 0; j < 8; j++)
                        acc[i][j] += am[i] * bm[j];
            } else {
#pragma unroll
                for (int i = 0; i < 8; i++)
#pragma unroll
                    for (int j = 0; j < 8; j++)
                        acc[i][j] = (am[i] != 0.f) ? fmaxf(acc[i][j], bm[j]) : acc[i][j];
            }
        }
        if (more) {
            const int nb = buf ^ 1;
            As[nb][ak+0][ar] = avn.x; As[nb][ak+1][ar] = avn.y; As[nb][ak+2][ar] = avn.z; As[nb][ak+3][ar] = avn.w;
            if (TB) {
                Bs[nb][ak+0][ar] = bvn.x; Bs[nb][ak+1][ar] = bvn.y; Bs[nb][ak+2][ar] = bvn.z; Bs[nb][ak+3][ar] = bvn.w;
            } else {
                *(float4*)&Bs[nb][bk][bn] = bvn;
            }
        }
        __syncthreads();
    }
#pragma unroll
    for (int i = 0; i < 8; i++) {
        float* crow = Cz + (size_t)(m0 + (ty << 3) + i) * ldc + n0 + (tx << 3);
        float4 r0; r0.x = acc[i][0]; r0.y = acc[i][1]; r0.z = acc[i][2]; r0.w = acc[i][3];
        float4 r1; r1.x = acc[i][4]; r1.y = acc[i][5]; r1.z = acc[i][6]; r1.w = acc[i][7];
        *(float4*)crow = r0;
        *(float4*)(crow + 4) = r1;
    }
}

// reduce S split partials (fixed order). OP=0 sum, OP=1 max.
template<int OP>
__global__ void k_red(const float* __restrict__ part, float* __restrict__ out, int MN, int S) {
    int i = blockIdx.x * 256 + threadIdx.x;
    if (i >= MN) return;
    float v = part[i];
    for (int s = 1; s < S; s++) {
        float w = part[(size_t)s * MN + i];
        v = OP ? fmaxf(v, w) : v + w;
    }
    out[i] = v;
}

// sum partials then scale by dinv[row]: y = dinv * (X@W)
__global__ void k_redscale(const float* __restrict__ part, float* __restrict__ out, int MN, int S) {
    int i = blockIdx.x * 256 + threadIdx.x;
    if (i >= MN) return;
    float v = part[i];
    for (int s = 1; s < S; s++) v += part[(size_t)s * MN + i];
    out[i] = g_dinv[i >> 8] * v;
}

// sum partials of A1@y then GCN epilogue: g = relu(dinv*sum + bias)
__global__ void k_redgcn(const float* __restrict__ part, const float* __restrict__ bias,
                         float* __restrict__ out, int MN, int S) {
    int i = blockIdx.x * 256 + threadIdx.x;
    if (i >= MN) return;
    float v = part[i];
    for (int s = 1; s < S; s++) v += part[(size_t)s * MN + i];
    out[i] = fmaxf(g_dinv[i >> 8] * v + bias[i & 255], 0.f);
}

// ---------------- level-0 sparse kernels --------------------------------------
__global__ void k_scatter(const int* __restrict__ ei, int ne, int n) {
    int e = blockIdx.x * blockDim.x + threadIdx.x;
    if (e < ne) g_A[(size_t)ei[e] * n + ei[ne + e]] = 1.0f;
}

__global__ void k_diag(int n) {
    int i = blockIdx.x * 256 + threadIdx.x;
    if (i < n) g_A[(size_t)i * n + i] = 1.0f;
}

// block per row: compact nonzero indices of A1 row (ascending, deterministic)
__global__ void k_buildnz(int n) {
    __shared__ int sc[256];
    int j = blockIdx.x, t = threadIdx.x;
    const float* row = g_A + (size_t)j * n;
    int seg = n >> 8;
    int base = t * seg;
    float vals[8];
    int cnt = 0;
#pragma unroll
    for (int i = 0; i < 8; i++) {
        float v = (i < seg) ? row[base + i] : 0.f;
        vals[i] = v;
        cnt += (v != 0.f);
    }
    sc[t] = cnt;
    __syncthreads();
    for (int o = 1; o < 256; o <<= 1) {
        int x = (t >= o) ? sc[t - o] : 0;
        __syncthreads();
        sc[t] += x;
        __syncthreads();
    }
    int pos = sc[t] - cnt;
    int total = sc[255];
    int* idx = g_nzidx + (size_t)j * CAP;
#pragma unroll
    for (int i = 0; i < 8; i++) {
        if (vals[i] != 0.f) {
            if (pos < CAP) idx[pos] = base + i;
            pos++;
        }
    }
    if (t == 0) {
        g_nzcnt[j] = (total > CAP) ? CAP : total;
        g_dinv[j] = 1.0f / sqrtf((float)total);
    }
}

__global__ void k_gcn_gather(const float* __restrict__ bias) {
    __shared__ int sidx[CAP];
    int j = blockIdx.x, c = threadIdx.x;
    int cnt = g_nzcnt[j];
    const int* idx = g_nzidx + (size_t)j * CAP;
    for (int t = c; t < cnt; t += 256) sidx[t] = idx[t];
    __syncthreads();
    float acc = 0.f;
#pragma unroll 4
    for (int t = 0; t < cnt; t++) acc += g_y[(size_t)sidx[t] * HID + c];
    g_g[(size_t)j * HID + c] = fmaxf(g_dinv[j] * acc + bias[c], 0.f);
}

__global__ void k_max_gather() {
    __shared__ int sidx[CAP];
    int j = blockIdx.x, c = threadIdx.x;
    int cnt = g_nzcnt[j];
    const int* idx = g_nzidx + (size_t)j * CAP;
    for (int t = c; t < cnt; t += 256) sidx[t] = idx[t];
    __syncthreads();
    float m = -FLT_MAX;
#pragma unroll 4
    for (int t = 0; t < cnt; t++) m = fmaxf(m, g_g[(size_t)sidx[t] * HID + c]);
    g_mm[(size_t)j * HID + c] = m;
}

__global__ void k_uv(const float* __restrict__ linb, const float* __restrict__ attw, int n) {
    int w = (blockIdx.x * blockDim.x + threadIdx.x) >> 5;
    int lane = threadIdx.x & 31;
    if (w >= n) return;
    float su = 0.f, sv = 0.f;
    const float* xq = g_xq + (size_t)w * HID;
    const float* gg = g_g + (size_t)w * HID;
    for (int c = lane; c < HID; c += 32) {
        su += (xq[c] + linb[c]) * attw[c];
        sv += gg[c] * attw[HID + c];
    }
    for (int o = 16; o; o >>= 1) {
        su += __shfl_down_sync(0xffffffffu, su, o);
        sv += __shfl_down_sync(0xffffffffu, sv, o);
    }
    if (lane == 0) { g_u[w] = su; g_v[w] = sv; }
}

__global__ void k_softmax_nz(const float* __restrict__ attb, int n) {
    int w = threadIdx.x >> 5, lane = threadIdx.x & 31;
    int j = blockIdx.x * 8 + w;
    if (j >= n) return;
    int cnt = g_nzcnt[j];
    const int* idx = g_nzidx + (size_t)j * CAP;
    float uj = g_u[j] + attb[0];
    float mx = -FLT_MAX;
    for (int t = lane; t < cnt; t += 32) {
        float r = g_v[idx[t]] + uj; r = (r >= 0.f) ? r : 0.2f * r;
        mx = fmaxf(mx, r);
    }
    for (int o = 16; o; o >>= 1) mx = fmaxf(mx, __shfl_xor_sync(0xffffffffu, mx, o));
    float sm = 0.f;
    for (int t = lane; t < cnt; t += 32) {
        float r = g_v[idx[t]] + uj; r = (r >= 0.f) ? r : 0.2f * r;
        sm += expf(r - mx);
    }
    for (int o = 16; o; o >>= 1) sm += __shfl_xor_sync(0xffffffffu, sm, o);
    float* sval = g_sval + (size_t)j * CAP;
    for (int t = lane; t < cnt; t += 32) {
        float r = g_v[idx[t]] + uj; r = (r >= 0.f) ? r : 0.2f * r;
        sval[t] = expf(r - mx) / sm;
    }
}

__global__ void k_wsum_gather() {
    __shared__ int sidx[CAP];
    __shared__ float sw[CAP];
    int j = blockIdx.x, c = threadIdx.x;
    int cnt = g_nzcnt[j];
    const int* idx = g_nzidx + (size_t)j * CAP;
    const float* sv = g_sval + (size_t)j * CAP;
    for (int t = c; t < cnt; t += 256) { sidx[t] = idx[t]; sw[t] = sv[t]; }
    __syncthreads();
    float acc = 0.f;
#pragma unroll 4
    for (int t = 0; t < cnt; t++) acc += sw[t] * g_g[(size_t)sidx[t] * HID + c];
    g_xnew[(size_t)j * HID + c] = acc;
}

__global__ void k_abc(const float* __restrict__ le1W, const float* __restrict__ le1b,
                      const float* __restrict__ le2W, const float* __restrict__ le3W,
                      const float* __restrict__ le3b, int n) {
    int w = (blockIdx.x * blockDim.x + threadIdx.x) >> 5;
    int lane = threadIdx.x & 31;
    if (w >= n) return;
    const float* xr = g_xnew + (size_t)w * HID;
    float sa = 0.f, sb = 0.f, sc = 0.f;
    for (int c = lane; c < HID; c += 32) {
        float xv = xr[c];
        sa += xv * le1W[c]; sb += xv * le2W[c]; sc += xv * le3W[c];
    }
    for (int o = 16; o; o >>= 1) {
        sa += __shfl_down_sync(0xffffffffu, sa, o);
        sb += __shfl_down_sync(0xffffffffu, sb, o);
        sc += __shfl_down_sync(0xffffffffu, sc, o);
    }
    if (lane == 0) { g_av[w] = sa + le1b[0]; g_bv[w] = sb; g_cv[w] = sc + le3b[0]; }
}

__global__ void k_fit_nz(int n) {
    int w = threadIdx.x >> 5, lane = threadIdx.x & 31;
    int j = blockIdx.x * 8 + w;
    if (j >= n) return;
    int cnt = g_nzcnt[j];
    const int* idx = g_nzidx + (size_t)j * CAP;
    float s = 0.f;
    for (int t = lane; t < cnt; t += 32) s += g_av[idx[t]];
    for (int o = 16; o; o >>= 1) s += __shfl_xor_sync(0xffffffffu, s, o);
    if (lane == 0) {
        float z = s - (float)cnt * g_bv[j] + g_cv[j];
        g_fit[j] = 1.0f / (1.0f + expf(-z));
    }
}

__global__ void k_spscatter(int k) {
    int q = blockIdx.x, t = threadIdx.x;
    int pj = g_perm[q];
    if (t < g_nzcnt[pj])
        g_SpT[(size_t)g_nzidx[(size_t)pj * CAP + t] * k + q] = g_sval[(size_t)pj * CAP + t];
}

__global__ void k_m2(int k) {
    __shared__ int sidx[CAP];
    int j = blockIdx.x, c = threadIdx.x;
    int cnt = g_nzcnt[j];
    const int* idx = g_nzidx + (size_t)j * CAP;
    for (int t = c; t < cnt; t += 256) sidx[t] = idx[t];
    __syncthreads();
    float4 acc = {0.f, 0.f, 0.f, 0.f};
#pragma unroll 2
    for (int t = 0; t < cnt; t++) {
        float4 v = ((const float4*)(g_SpT + (size_t)sidx[t] * k))[c];
        acc.x += v.x; acc.y += v.y; acc.z += v.z; acc.w += v.w;
    }
    ((float4*)(g_M2T + (size_t)j * k))[c] = acc;
}

__global__ void k_acg(int k) {
    __shared__ int sidx[CAP];
    __shared__ float sw[CAP];
    int p = blockIdx.x, c = threadIdx.x;
    int pp = g_perm[p];
    int cnt = g_nzcnt[pp];
    const int* idx = g_nzidx + (size_t)pp * CAP;
    const float* sv = g_sval + (size_t)pp * CAP;
    for (int t = c; t < cnt; t += 256) { sidx[t] = idx[t]; sw[t] = sv[t]; }
    __syncthreads();
    float4 acc = {0.f, 0.f, 0.f, 0.f};
#pragma unroll 2
    for (int t = 0; t < cnt; t++) {
        float w = sw[t];
        float4 v = ((const float4*)(g_M2T + (size_t)sidx[t] * k))[c];
        acc.x += w * v.x; acc.y += w * v.y; acc.z += w * v.z; acc.w += w * v.w;
    }
    ((float4*)(g_Ac + (size_t)p * k))[c] = acc;
}

// ---------------- dense-path kernels (levels >= 1; g_A holds A1) --------------
__global__ void k_dinv(int n) {
    int j = blockIdx.x, tid = threadIdx.x;
    __shared__ float red[256];
    const float* row = g_A + (size_t)j * n;
    float s = 0.f;
    for (int i = tid; i < n; i += 256) s += row[i];
    red[tid] = s; __syncthreads();
    for (int o = 128; o; o >>= 1) { if (tid < o) red[tid] += red[tid + o]; __syncthreads(); }
    if (tid == 0) g_dinv[j] = 1.0f / sqrtf(red[0]);
}

__global__ void k_softmax(const float* __restrict__ attb, int n) {
    int j = blockIdx.x, tid = threadIdx.x;
    __shared__ float red[256];
    __shared__ float s_mx, s_sum;
    const float* mrow = g_A + (size_t)j * n;
    float uj = g_u[j] + attb[0];
    float mx = -FLT_MAX;
    for (int i = tid; i < n; i += 256) {
        if (mrow[i] != 0.f) {
            float r = g_v[i] + uj; r = (r >= 0.f) ? r : 0.2f * r;
            mx = fmaxf(mx, r);
        }
    }
    red[tid] = mx; __syncthreads();
    for (int o = 128; o; o >>= 1) { if (tid < o) red[tid] = fmaxf(red[tid], red[tid + o]); __syncthreads(); }
    if (tid == 0) s_mx = red[0];
    __syncthreads();
    float sm = 0.f;
    for (int i = tid; i < n; i += 256) {
        if (mrow[i] != 0.f) {
            float r = g_v[i] + uj; r = (r >= 0.f) ? r : 0.2f * r;
            sm += expf(r - s_mx);
        }
    }
    red[tid] = sm; __syncthreads();
    for (int o = 128; o; o >>= 1) { if (tid < o) red[tid] += red[tid + o]; __syncthreads(); }
    if (tid == 0) s_sum = red[0];
    __syncthreads();
    float* srow = g_scoreT + (size_t)j * n;
    for (int i = tid; i < n; i += 256) {
        float val = 0.f;
        if (mrow[i] != 0.f) {
            float r = g_v[i] + uj; r = (r >= 0.f) ? r : 0.2f * r;
            val = expf(r - s_mx) / s_sum;
        }
        srow[i] = val;
    }
}

__global__ void k_fit(int n) {
    int j = blockIdx.x, tid = threadIdx.x;
    __shared__ float rs[256], rc[256];
    const float* mrow = g_A + (size_t)j * n;
    float s = 0.f, cn = 0.f;
    for (int i = tid; i < n; i += 256) {
        if (mrow[i] != 0.f) { s += g_av[i]; cn += 1.f; }
    }
    rs[tid] = s; rc[tid] = cn; __syncthreads();
    for (int o = 128; o; o >>= 1) {
        if (tid < o) { rs[tid] += rs[tid + o]; rc[tid] += rc[tid + o]; }
        __syncthreads();
    }
    if (tid == 0) {
        float z = rs[0] - rc[0] * g_bv[j] + g_cv[j];
        g_fit[j] = 1.0f / (1.0f + expf(-z));
    }
}

// bitonic sort on packed 64-bit keys: (fitness_bits << 32) | ~index
__global__ void k_sort(int n, int k) {
    __shared__ unsigned long long sk[NMAX];
    int tid = threadIdx.x;
    for (int i = tid; i < n; i += blockDim.x)
        sk[i] = ((unsigned long long)__float_as_uint(g_fit[i]) << 32) | (unsigned)(~i);
    __syncthreads();
    for (int size = 2; size <= n; size <<= 1) {
        for (int stride = size >> 1; stride > 0; stride >>= 1) {
            for (int i = tid; i < n; i += blockDim.x) {
                int j = i ^ stride;
                if (j > i) {
                    bool desc = ((i & size) == 0);
                    unsigned long long a = sk[i], b = sk[j];
                    if (desc ? (a < b) : (a > b)) { sk[i] = b; sk[j] = a; }
                }
            }
            __syncthreads();
        }
    }
    for (int t = tid; t < k; t += blockDim.x) {
        unsigned long long v = sk[t];
        g_perm[t] = (int)(~(unsigned)v);
        g_fvals[t] = __uint_as_float((unsigned)(v >> 32));
    }
}

__global__ void k_pool(int k) {
    int q = blockIdx.x, c = threadIdx.x;
    g_h[(size_t)q * HID + c] = g_xnew[(size_t)g_perm[q] * HID + c] * g_fvals[q];
}

__global__ void k_readout(int k) {
    __shared__ float rs[256], rm[256];
    int c = blockIdx.x, tid = threadIdx.x;
    float s = 0.f, m = -FLT_MAX;
    for (int q = tid; q < k; q += 256) {
        float v = g_h[(size_t)q * HID + c];
        s += v; m = fmaxf(m, v);
    }
    rs[tid] = s; rm[tid] = m; __syncthreads();
    for (int o = 128; o; o >>= 1) {
        if (tid < o) { rs[tid] += rs[tid + o]; rm[tid] = fmaxf(rm[tid], rm[tid + o]); }
        __syncthreads();
    }
    if (tid == 0) {
        g_ro[c] += rs[0] / (float)k;
        g_ro[HID + c] += rm[0];
    }
}

__global__ void k_gatherSpT(int n, int k) {
    int i = blockIdx.x * 256 + threadIdx.x;
    int q = blockIdx.y;
    g_SpT[(size_t)q * n + i] = g_scoreT[(size_t)g_perm[q] * n + i];
}

// A <- A1 of coarsened graph: off-diag from Ac, diag = 1
__global__ void k_setA(int k) {
    int idx = blockIdx.x * blockDim.x + threadIdx.x;
    if (idx < k * k) {
        int p = idx / k, q = idx - p * k;
        g_A[idx] = (p == q) ? 1.f : g_Ac[idx];
    }
}

__global__ void k_head(const float* __restrict__ l1W, const float* __restrict__ l1b,
                       const float* __restrict__ l2W, const float* __restrict__ l2b,
                       float* __restrict__ out) {
    __shared__ float hid[HID];
    __shared__ float lg[16];
    int t = threadIdx.x;
    float s = l1b[t];
    for (int kk = 0; kk < 2 * HID; kk++) s += g_ro[kk] * l1W[kk * HID + t];
    hid[t] = fmaxf(s, 0.f);
    __syncthreads();
    if (t < 10) {
        float s2 = l2b[t];
        for (int c = 0; c < HID; c++) s2 += hid[c] * l2W[c * 10 + t];
        lg[t] = s2;
    }
    __syncthreads();
    if (t == 0) {
        float m = lg[0];
        for (int i = 1; i < 10; i++) m = fmaxf(m, lg[i]);
        float sm = 0.f;
        for (int i = 0; i < 10; i++) sm += expf(lg[i] - m);
        float ls = logf(sm);
        for (int i = 0; i < 10; i++) out[i] = lg[i] - m - ls;
    }
}

// ---------------- launcher ---------------------------------------------------
extern "C" void kernel_launch(void* const* d_in, const int* in_sizes, int n_in,
                              void* d_out, int out_size) {
    const float* x    = (const float*)d_in[0];
    const int*   ei   = (const int*)d_in[1];
    const float* W1   = (const float*)d_in[2];
    const float* b1   = (const float*)d_in[3];
    const float* W2   = (const float*)d_in[4];
    const float* b2   = (const float*)d_in[5];
    const float* linW = (const float*)d_in[6];
    const float* linb = (const float*)d_in[7];
    const float* attw = (const float*)d_in[8];
    const float* attb = (const float*)d_in[9];
    const float* le1W = (const float*)d_in[10];
    const float* le1b = (const float*)d_in[11];
    const float* le2W = (const float*)d_in[12];
    const float* le3W = (const float*)d_in[13];
    const float* le3b = (const float*)d_in[14];
    const float* l1W  = (const float*)d_in[15];
    const float* l1b  = (const float*)d_in[16];
    const float* l2W  = (const float*)d_in[17];
    const float* l2b  = (const float*)d_in[18];

    float *pA, *pscoreT, *pSpT, *pM2T, *pAc, *pPart;
    float *py, *pmm, *pxq, *pxnew, *ph, *pg, *pro;
    cudaGetSymbolAddress((void**)&pA, g_A);
    cudaGetSymbolAddress((void**)&pscoreT, g_scoreT);
    cudaGetSymbolAddress((void**)&pSpT, g_SpT);
    cudaGetSymbolAddress((void**)&pM2T, g_M2T);
    cudaGetSymbolAddress((void**)&pAc, g_Ac);
    cudaGetSymbolAddress((void**)&pPart, g_part);
    cudaGetSymbolAddress((void**)&py, g_y);
    cudaGetSymbolAddress((void**)&pmm, g_mm);
    cudaGetSymbolAddress((void**)&pxq, g_xq);
    cudaGetSymbolAddress((void**)&pxnew, g_xnew);
    cudaGetSymbolAddress((void**)&ph, g_h);
    cudaGetSymbolAddress((void**)&pg, g_g);
    cudaGetSymbolAddress((void**)&pro, g_ro);

    int n = 2048;
    int ne = in_sizes[1] / 2;

    cudaMemsetAsync(pA, 0, (size_t)n * n * sizeof(float));
    cudaMemsetAsync(pro, 0, 2 * HID * sizeof(float));
    k_scatter<<<(ne + 255) / 256, 256>>>(ei, ne, n);
    k_diag<<<(n + 255) / 256, 256>>>(n);

    const float* X = x;
    int f_in = 128;

    for (int lvl = 0; lvl < 3; lvl++) {
        const float* W  = lvl ? W2 : W1;
        const float* bb = lvl ? b2 : b1;
        int k = n / 2;
        int nh = n * HID;
        int rg = (nh + 255) / 256;

        if (lvl == 0) {
            // ---- sparse level-0 path ----
            k_buildnz<<<n, 256>>>(n);
            k_gemm<false,0><<<dim3(HID/128, n/128, 4), 256>>>(X, W, pPart, n, HID, f_in/4, f_in, HID, HID);
            k_redscale<<<rg, 256>>>(pPart, py, nh, 4);
            k_gcn_gather<<<n, 256>>>(bb);
            k_max_gather<<<n, 256>>>();
            k_gemm<false,0><<<dim3(HID/128, n/128, 4), 256>>>(pmm, linW, pPart, n, HID, HID/4, HID, HID, HID);
            k_red<0><<<rg, 256>>>(pPart, pxq, nh, 4);
            k_uv<<<(n * 32 + 255) / 256, 256>>>(linb, attw, n);
            k_softmax_nz<<<n / 8, 256>>>(attb, n);
            k_wsum_gather<<<n, 256>>>();
            k_abc<<<(n * 32 + 255) / 256, 256>>>(le1W, le1b, le2W, le3W, le3b, n);
            k_fit_nz<<<n / 8, 256>>>(n);
            k_sort<<<1, 1024>>>(n, k);
            k_pool<<<k, 256>>>(k);
            k_readout<<<HID, 256>>>(k);
            cudaMemsetAsync(pSpT, 0, (size_t)n * k * sizeof(float));
            k_spscatter<<<k, 256>>>(k);
            k_m2<<<n, 256>>>(k);
            k_acg<<<k, 256>>>(k);
            k_setA<<<(k * k + 255) / 256, 256>>>(k);
        } else {
            // ---- dense path (g_A holds A1) ----
            const int S = 8;
            dim3 gS(HID/128, n/128, S);

            k_dinv<<<n, 256>>>(n);
            // y = dinv * (X@W)
            k_gemm<false,0><<<gS, 256>>>(X, W, pPart, n, HID, HID/S, HID, HID, HID);
            k_redscale<<<rg, 256>>>(pPart, py, nh, S);
            // g = relu(dinv * (A1@y) + b)
            k_gemm<false,0><<<gS, 256>>>(pA, py, pPart, n, HID, n/S, n, HID, HID);
            k_redgcn<<<rg, 256>>>(pPart, bb, pg, nh, S);
            // mm = masked max over A1 != 0
            k_gemm<false,1><<<gS, 256>>>(pA, pg, pPart, n, HID, n/S, n, HID, HID);
            k_red<1><<<rg, 256>>>(pPart, pmm, nh, S);
            // xq = mm@linW
            k_gemm<false,0><<<gS, 256>>>(pmm, linW, pPart, n, HID, HID/S, HID, HID, HID);
            k_red<0><<<rg, 256>>>(pPart, pxq, nh, S);
            k_uv<<<(n * 32 + 255) / 256, 256>>>(linb, attw, n);
            k_softmax<<<n, 256>>>(attb, n);
            // xnew = scoreT@g
            k_gemm<false,0><<<gS, 256>>>(pscoreT, pg, pPart, n, HID, n/S, n, HID, HID);
            k_red<0><<<rg, 256>>>(pPart, pxnew, nh, S);

            k_abc<<<(n * 32 + 255) / 256, 256>>>(le1W, le1b, le2W, le3W, le3b, n);
            k_fit<<<n, 256>>>(n);
            k_sort<<<1, 1024>>>(n, k);
            k_pool<<<k, 256>>>(k);
            k_readout<<<HID, 256>>>(k);

            if (lvl < 2) {
                k_gatherSpT<<<dim3(n / 256, k), 256>>>(n, k);
                // M2T = SpT @ binarize(A1)
                k_gemm<false,2><<<dim3(n/128, k/128, 4), 256>>>(pSpT, pA, pPart, k, n, n/4, n, n, n);
                k_red<0><<<(k * n + 255) / 256, 256>>>(pPart, pM2T, k * n, 4);
                // Ac = SpT @ M2T^T
                k_gemm<true,0><<<dim3(k/128, k/128, 8), 256>>>(pSpT, pM2T, pPart, k, k, n/8, n, n, k);
                k_red<0><<<(k * k + 255) / 256, 256>>>(pPart, pAc, k * k, 8);
                k_setA<<<(k * k + 255) / 256, 256>>>(k);
            }
        }

        X = ph; f_in = HID; n = k;
    }

    k_head<<<1, 256>>>(l1W, l1b, l2W, l2b, (float*)d_out);
}